// round 5
// baseline (speedup 1.0000x reference)
#include <cuda_runtime.h>
#include <math.h>

#define BB 8
#define AA 49104
#define MM 50
#define KK 80
#define TPB 256
#define ANCH_PER_BLK 256
#define NBLKX ((AA + ANCH_PER_BLK - 1) / ANCH_PER_BLK)   // 192
#define NBLKS (NBLKX * BB)                               // 1536

// zero-initialized at module load; finalizer re-zeros after each consume,
// so every graph replay starts clean.
__device__ float g_cls_raw[BB];
__device__ float g_reg_raw[BB];
__device__ int   g_numpos[BB];
__device__ unsigned int g_done;

__device__ __forceinline__ float smooth_l1(float d) {
    const float BETA = 1.0f / 9.0f;
    float ad = fabsf(d);
    return (ad <= BETA) ? (4.5f * ad * ad) : (ad - 0.5f * BETA);
}

// focal bulk term for one float4 of probabilities: sum p^2 * log2(1-p)
__device__ __forceinline__ float focal4(float4 p4) {
    return p4.x * p4.x * __log2f(1.0f - p4.x)
         + p4.y * p4.y * __log2f(1.0f - p4.y)
         + p4.z * p4.z * __log2f(1.0f - p4.z)
         + p4.w * p4.w * __log2f(1.0f - p4.w);
}

__global__ __launch_bounds__(TPB, 6) void retina_fused_kernel(
    const float* __restrict__ logits,   // (B,A,K)
    const float* __restrict__ regp,     // (B,A,4)
    const float* __restrict__ anchors,  // (A,4)
    const float* __restrict__ boxes,    // (B,M,4)
    const int*   __restrict__ cls,      // (B,M)
    float* __restrict__ out)
{
    const int b = blockIdx.y;
    const int tid = threadIdx.x;
    const int aStart = blockIdx.x * ANCH_PER_BLK;
    const int a = aStart + tid;
    const int aCnt = min(ANCH_PER_BLK, AA - aStart);

    __shared__ float4 sbox[MM];            // box coords
    __shared__ float4 saux[MM];            // (2/7)sb, (1/3)sb, sb, cls-bits
    __shared__ int    splist[ANCH_PER_BLK];
    __shared__ int    siglist[ANCH_PER_BLK];
    __shared__ int    spcnt, sigcnt;
    __shared__ float  wsum[8], wsum2[8];

    if (tid == 0) { spcnt = 0; sigcnt = 0; }
    if (tid < MM) {
        float4 bx = ((const float4*)boxes)[b * MM + tid];
        float sb = (bx.z - bx.x) * (bx.w - bx.y);
        sbox[tid] = bx;
        float4 au;
        au.x = sb * (2.0f / 7.0f);   // 0.4/(1+0.4) * sb
        au.y = sb * (1.0f / 3.0f);   // 0.5/(1+0.5) * sb
        au.z = sb;
        au.w = __int_as_float(cls[b * MM + tid]);
        saux[tid] = au;
    }

    float s = 0.0f;      // classification partial (units of p^2*log2(...))
    float rsum = 0.0f;   // regression partial

    // ---------- phase A: unconditional coalesced focal sweep ----------
    // Starts streaming immediately; no dependency on the screen. Ignore
    // anchors (iou in [0.4,0.5)) are rare and get subtracted in phase C.
    const float4* tile4 = (const float4*)(logits + ((size_t)b * AA + aStart) * KK);
    if (aCnt == ANCH_PER_BLK) {
        #pragma unroll 5
        for (int k = 0; k < ANCH_PER_BLK * (KK / 4) / TPB; ++k)
            s += focal4(tile4[tid + k * TPB]);
    } else {
        const int n4 = aCnt * (KK / 4);
        for (int i = tid; i < n4; i += TPB)
            s += focal4(tile4[i]);
    }

    __syncthreads();   // sbox/saux visible; counters initialized

    // ---------- phase B: cheap screen (10 ops/box via FFMA fusion) ----------
    // iou >= t  <=>  inter >= t/(1+t)*(sa+sb); inter - c = fma(iw, ih, -c).
    // Only iw is clamped: if ih<0 the fma under-estimates, and both
    // thresholds are strictly positive, so decisions are unchanged. Padded
    // boxes (-1) give iw=0 -> candidate -au <= 0: never flips anything.
    if (a < AA) {
        float4 an = ((const float4*)anchors)[a];
        const float ax1 = an.x, ay1 = an.y, ax2 = an.z, ay2 = an.w;
        const float sa = (ax2 - ax1) * (ay2 - ay1);

        float m4 = -1e30f, m5 = -1e30f;
        #pragma unroll 10
        for (int j = 0; j < MM; ++j) {
            float4 bx = sbox[j];
            float4 au = saux[j];
            float iw = fmaxf(fminf(ax2, bx.z) - fmaxf(ax1, bx.x), 0.0f);
            float ih = fminf(ay2, bx.w) - fmaxf(ay1, bx.y);
            m4 = fmaxf(m4, __fmaf_rn(iw, ih, -au.x));
            m5 = fmaxf(m5, __fmaf_rn(iw, ih, -au.y));
        }
        const bool pos = (m5 >= sa * (1.0f / 3.0f));   // iou_max >= 0.5
        const bool neg = (m4 <  sa * (2.0f / 7.0f));   // iou_max < 0.4
        if (pos) splist[atomicAdd(&spcnt, 1)] = tid;
        else if (!neg) siglist[atomicAdd(&sigcnt, 1)] = tid;
    }
    __syncthreads();
    const int nposblk = spcnt;
    const int nignblk = sigcnt;

    // ---------- phase C: compacted ignore-row subtraction (L1-hot) ----------
    for (int i = tid; i < nignblk; i += TPB) {
        const float4* row4 = tile4 + siglist[i] * (KK / 4);
        float t = 0.0f;
        #pragma unroll
        for (int k = 0; k < KK / 4; ++k) t += focal4(row4[k]);
        s -= t;
    }

    // ---------- phase D: compacted positives (usually < 1 warp) ----------
    for (int i = tid; i < nposblk; i += TPB) {
        const int at = splist[i];
        const int ag = aStart + at;
        float4 an = ((const float4*)anchors)[ag];   // L1 hit
        const float ax1 = an.x, ay1 = an.y, ax2 = an.z, ay2 = an.w;
        const float aw = ax2 - ax1, ah = ay2 - ay1;
        const float sa = aw * ah;

        // division-free argmax of iou (first-max semantics preserved by '>')
        float bi = -1.0f, bu = 1.0f;
        int bj = 0;
        for (int j = 0; j < MM; ++j) {
            float4 bx = sbox[j];
            float iw = fmaxf(fminf(ax2, bx.z) - fmaxf(ax1, bx.x), 0.0f);
            float ih = fmaxf(fminf(ay2, bx.w) - fmaxf(ay1, bx.y), 0.0f);
            float inter = iw * ih;
            float ua = fmaxf(sa + saux[j].z - inter, 1e-8f);
            if (inter * bu > bi * ua) { bi = inter; bu = ua; bj = j; }
        }

        // focal correction on the positive class
        int c = __float_as_int(saux[bj].w) - 1;
        float praw = __ldg(logits + ((size_t)b * AA + ag) * KK + c);
        float p = fminf(fmaxf(praw, 1e-4f), 1.0f - 1e-4f);
        float q = 1.0f - p;
        s += (1.0f / 3.0f) * q * q * __log2f(p) - p * p * __log2f(q);

        // regression smooth-L1
        float4 gb = sbox[bj];
        float acx = ax1 + 0.5f * aw;
        float acy = ay1 + 0.5f * ah;
        float gw0 = gb.z - gb.x, gh0 = gb.w - gb.y;
        float gcx = gb.x + 0.5f * gw0;
        float gcy = gb.y + 0.5f * gh0;
        float gw = fmaxf(gw0, 1.0f), gh = fmaxf(gh0, 1.0f);
        float4 rp = ((const float4*)regp)[b * AA + ag];
        float t0 = ((gcx - acx) / aw) * 10.0f;
        float t1 = ((gcy - acy) / ah) * 10.0f;
        float t2 = logf(gw / aw) * 5.0f;
        float t3 = logf(gh / ah) * 5.0f;
        rsum += smooth_l1(t0 - rp.x) + smooth_l1(t1 - rp.y)
              + smooth_l1(t2 - rp.z) + smooth_l1(t3 - rp.w);
    }

    // ---------- phase E: block reduction, one atomic each ----------
    #pragma unroll
    for (int o = 16; o > 0; o >>= 1) {
        s    += __shfl_down_sync(0xffffffffu, s, o);
        rsum += __shfl_down_sync(0xffffffffu, rsum, o);
    }
    int lane = tid & 31, wid = tid >> 5;
    if (lane == 0) { wsum[wid] = s; wsum2[wid] = rsum; }
    __syncthreads();

    if (tid == 0) {
        float t = 0.0f, t2 = 0.0f;
        #pragma unroll
        for (int i = 0; i < 8; ++i) { t += wsum[i]; t2 += wsum2[i]; }
        if (t != 0.0f)  atomicAdd(&g_cls_raw[b], t);
        if (t2 != 0.0f) atomicAdd(&g_reg_raw[b], t2);
        if (nposblk)    atomicAdd(&g_numpos[b], nposblk);

        // ---------- phase F: last block finalizes + resets ----------
        __threadfence();
        unsigned int prev = atomicAdd(&g_done, 1u);
        if (prev == NBLKS - 1) {
            float cm = 0.0f, rm = 0.0f;
            #pragma unroll
            for (int bb = 0; bb < BB; ++bb) {
                float np = fmaxf((float)g_numpos[bb], 1.0f);
                cm += (-0.75f * 0.69314718055994531f) * g_cls_raw[bb] / np;
                rm += g_reg_raw[bb] / (4.0f * np);
                g_cls_raw[bb] = 0.0f;
                g_reg_raw[bb] = 0.0f;
                g_numpos[bb] = 0;
            }
            cm *= (1.0f / (float)BB);
            rm *= (1.0f / (float)BB);
            out[0] = cm;
            out[1] = rm;
            out[2] = cm + rm;
            g_done = 0u;
        }
    }
}

extern "C" void kernel_launch(void* const* d_in, const int* in_sizes, int n_in,
                              void* d_out, int out_size) {
    const float* logits  = (const float*)d_in[0];
    const float* regp    = (const float*)d_in[1];
    const float* anchors = (const float*)d_in[2];
    const float* boxes   = (const float*)d_in[3];
    const int*   cls     = (const int*)d_in[4];
    float* out = (float*)d_out;

    dim3 grid(NBLKX, BB);
    retina_fused_kernel<<<grid, TPB>>>(logits, regp, anchors, boxes, cls, out);
}

// round 6
// speedup vs baseline: 1.0467x; 1.0467x over previous
#include <cuda_runtime.h>
#include <math.h>

#define BB 8
#define AA 49104
#define MM 50
#define KK 80
#define TPB 256
#define ANCH_PER_BLK 256
#define NBLKX ((AA + ANCH_PER_BLK - 1) / ANCH_PER_BLK)   // 192
#define NBLKS (NBLKX * BB)                               // 1536

// zero-initialized at module load; finalizer re-zeros after each consume,
// so every graph replay starts clean.
__device__ float g_cls_raw[BB];
__device__ float g_reg_raw[BB];
__device__ int   g_numpos[BB];
__device__ unsigned int g_done;

__device__ __forceinline__ float smooth_l1(float d) {
    const float BETA = 1.0f / 9.0f;
    float ad = fabsf(d);
    return (ad <= BETA) ? (4.5f * ad * ad) : (ad - 0.5f * BETA);
}

// focal bulk term for one float4 of probabilities: sum p^2 * log2(1-p)
__device__ __forceinline__ float focal4(float4 p4) {
    return p4.x * p4.x * __log2f(1.0f - p4.x)
         + p4.y * p4.y * __log2f(1.0f - p4.y)
         + p4.z * p4.z * __log2f(1.0f - p4.z)
         + p4.w * p4.w * __log2f(1.0f - p4.w);
}

__global__ __launch_bounds__(TPB, 6) void retina_fused_kernel(
    const float* __restrict__ logits,   // (B,A,K)
    const float* __restrict__ regp,     // (B,A,4)
    const float* __restrict__ anchors,  // (A,4)
    const float* __restrict__ boxes,    // (B,M,4)
    const int*   __restrict__ cls,      // (B,M)
    float* __restrict__ out)
{
    const int b = blockIdx.y;
    const int tid = threadIdx.x;
    const int aStart = blockIdx.x * ANCH_PER_BLK;
    const int a = aStart + tid;
    const int aCnt = min(ANCH_PER_BLK, AA - aStart);

    __shared__ float4 sbox[MM];            // box coords
    __shared__ float4 saux[MM];            // (2/7)sb, (1/3)sb, sb, cls-bits
    __shared__ int    splist[ANCH_PER_BLK];
    __shared__ int    siglist[ANCH_PER_BLK];
    __shared__ int    spcnt, sigcnt;
    __shared__ float  wsum[8], wsum2[8];

    if (tid == 0) { spcnt = 0; sigcnt = 0; }
    if (tid < MM) {
        float4 bx = ((const float4*)boxes)[b * MM + tid];
        float sb = (bx.z - bx.x) * (bx.w - bx.y);
        sbox[tid] = bx;
        float4 au;
        au.x = sb * (2.0f / 7.0f);   // 0.4/(1+0.4) * sb
        au.y = sb * (1.0f / 3.0f);   // 0.5/(1+0.5) * sb
        au.z = sb;
        au.w = __int_as_float(cls[b * MM + tid]);
        saux[tid] = au;
    }
    __syncthreads();

    float s = 0.0f;      // classification partial (units of p^2*log2(...))
    float rsum = 0.0f;   // regression partial

    // ---------- phase 1: cheap screen (10 ops/box via FFMA fusion) ----------
    // iou >= t  <=>  inter >= t/(1+t)*(sa+sb); inter - c = fma(iw, ih, -c).
    // Only iw is clamped: if ih<0 the fma under-estimates, and both
    // thresholds are strictly positive, so decisions are unchanged. Padded
    // boxes (-1) give iw=0 -> candidate -au <= 0: never flips anything.
    if (a < AA) {
        float4 an = ((const float4*)anchors)[a];
        const float ax1 = an.x, ay1 = an.y, ax2 = an.z, ay2 = an.w;
        const float sa = (ax2 - ax1) * (ay2 - ay1);

        float m4 = -1e30f, m5 = -1e30f;
        #pragma unroll 10
        for (int j = 0; j < MM; ++j) {
            float4 bx = sbox[j];
            float4 au = saux[j];
            float iw = fmaxf(fminf(ax2, bx.z) - fmaxf(ax1, bx.x), 0.0f);
            float ih = fminf(ay2, bx.w) - fmaxf(ay1, bx.y);
            m4 = fmaxf(m4, __fmaf_rn(iw, ih, -au.x));
            m5 = fmaxf(m5, __fmaf_rn(iw, ih, -au.y));
        }
        const bool pos = (m5 >= sa * (1.0f / 3.0f));   // iou_max >= 0.5
        const bool neg = (m4 <  sa * (2.0f / 7.0f));   // iou_max < 0.4
        if (pos) splist[atomicAdd(&spcnt, 1)] = tid;
        else if (!neg) siglist[atomicAdd(&sigcnt, 1)] = tid;
    }
    __syncthreads();
    const int nposblk = spcnt;
    const int nignblk = sigcnt;

    // ---------- phase 2: unconditional coalesced focal sweep ----------
    // No per-anchor weight: ignore rows are rare and subtracted in phase 3.
    const float4* tile4 = (const float4*)(logits + ((size_t)b * AA + aStart) * KK);
    {
        float s1 = 0.0f;
        if (aCnt == ANCH_PER_BLK) {
            #pragma unroll 5
            for (int k = 0; k < ANCH_PER_BLK * (KK / 4) / TPB; k += 2) {
                s  += focal4(tile4[tid + k * TPB]);
                s1 += focal4(tile4[tid + (k + 1) * TPB]);
            }
        } else {
            const int n4 = aCnt * (KK / 4);
            for (int i = tid; i < n4; i += TPB)
                s1 += focal4(tile4[i]);
        }
        s += s1;
    }

    // ---------- phase 3: compacted ignore-row subtraction (L1-hot) ----------
    for (int i = tid; i < nignblk; i += TPB) {
        const float4* row4 = tile4 + siglist[i] * (KK / 4);
        float t = 0.0f;
        #pragma unroll
        for (int k = 0; k < KK / 4; ++k) t += focal4(row4[k]);
        s -= t;
    }

    // ---------- phase 4: compacted positives (usually < 1 warp) ----------
    for (int i = tid; i < nposblk; i += TPB) {
        const int at = splist[i];
        const int ag = aStart + at;
        float4 an = ((const float4*)anchors)[ag];   // L1 hit
        const float ax1 = an.x, ay1 = an.y, ax2 = an.z, ay2 = an.w;
        const float aw = ax2 - ax1, ah = ay2 - ay1;
        const float sa = aw * ah;

        // division-free argmax of iou (first-max semantics preserved by '>')
        float bi = -1.0f, bu = 1.0f;
        int bj = 0;
        for (int j = 0; j < MM; ++j) {
            float4 bx = sbox[j];
            float iw = fmaxf(fminf(ax2, bx.z) - fmaxf(ax1, bx.x), 0.0f);
            float ih = fmaxf(fminf(ay2, bx.w) - fmaxf(ay1, bx.y), 0.0f);
            float inter = iw * ih;
            float ua = fmaxf(sa + saux[j].z - inter, 1e-8f);
            if (inter * bu > bi * ua) { bi = inter; bu = ua; bj = j; }
        }

        // focal correction on the positive class
        int c = __float_as_int(saux[bj].w) - 1;
        float praw = __ldg(logits + ((size_t)b * AA + ag) * KK + c);
        float p = fminf(fmaxf(praw, 1e-4f), 1.0f - 1e-4f);
        float q = 1.0f - p;
        s += (1.0f / 3.0f) * q * q * __log2f(p) - p * p * __log2f(q);

        // regression smooth-L1
        float4 gb = sbox[bj];
        float acx = ax1 + 0.5f * aw;
        float acy = ay1 + 0.5f * ah;
        float gw0 = gb.z - gb.x, gh0 = gb.w - gb.y;
        float gcx = gb.x + 0.5f * gw0;
        float gcy = gb.y + 0.5f * gh0;
        float gw = fmaxf(gw0, 1.0f), gh = fmaxf(gh0, 1.0f);
        float4 rp = ((const float4*)regp)[b * AA + ag];
        float t0 = ((gcx - acx) / aw) * 10.0f;
        float t1 = ((gcy - acy) / ah) * 10.0f;
        float t2 = logf(gw / aw) * 5.0f;
        float t3 = logf(gh / ah) * 5.0f;
        rsum += smooth_l1(t0 - rp.x) + smooth_l1(t1 - rp.y)
              + smooth_l1(t2 - rp.z) + smooth_l1(t3 - rp.w);
    }

    // ---------- phase 5: block reduction, one atomic each ----------
    #pragma unroll
    for (int o = 16; o > 0; o >>= 1) {
        s    += __shfl_down_sync(0xffffffffu, s, o);
        rsum += __shfl_down_sync(0xffffffffu, rsum, o);
    }
    int lane = tid & 31, wid = tid >> 5;
    if (lane == 0) { wsum[wid] = s; wsum2[wid] = rsum; }
    __syncthreads();

    if (tid == 0) {
        float t = 0.0f, t2 = 0.0f;
        #pragma unroll
        for (int i = 0; i < 8; ++i) { t += wsum[i]; t2 += wsum2[i]; }
        if (t != 0.0f)  atomicAdd(&g_cls_raw[b], t);
        if (t2 != 0.0f) atomicAdd(&g_reg_raw[b], t2);
        if (nposblk)    atomicAdd(&g_numpos[b], nposblk);

        // ---------- phase 6: last block finalizes + resets ----------
        __threadfence();
        unsigned int prev = atomicAdd(&g_done, 1u);
        if (prev == NBLKS - 1) {
            float cm = 0.0f, rm = 0.0f;
            #pragma unroll
            for (int bb = 0; bb < BB; ++bb) {
                float np = fmaxf((float)g_numpos[bb], 1.0f);
                cm += (-0.75f * 0.69314718055994531f) * g_cls_raw[bb] / np;
                rm += g_reg_raw[bb] / (4.0f * np);
                g_cls_raw[bb] = 0.0f;
                g_reg_raw[bb] = 0.0f;
                g_numpos[bb] = 0;
            }
            cm *= (1.0f / (float)BB);
            rm *= (1.0f / (float)BB);
            out[0] = cm;
            out[1] = rm;
            out[2] = cm + rm;
            g_done = 0u;
        }
    }
}

extern "C" void kernel_launch(void* const* d_in, const int* in_sizes, int n_in,
                              void* d_out, int out_size) {
    const float* logits  = (const float*)d_in[0];
    const float* regp    = (const float*)d_in[1];
    const float* anchors = (const float*)d_in[2];
    const float* boxes   = (const float*)d_in[3];
    const int*   cls     = (const int*)d_in[4];
    float* out = (float*)d_out;

    dim3 grid(NBLKX, BB);
    retina_fused_kernel<<<grid, TPB>>>(logits, regp, anchors, boxes, cls, out);
}

// round 7
// speedup vs baseline: 1.1524x; 1.1010x over previous
#include <cuda_runtime.h>
#include <math.h>

#define BB 8
#define AA 49104
#define MM 50
#define KK 80
#define TPB 256
#define ANCH_PER_BLK 256
#define NBLKX ((AA + ANCH_PER_BLK - 1) / ANCH_PER_BLK)   // 192
#define NBLKS (NBLKX * BB)                               // 1536

// zero-initialized at module load; finalizer re-zeros after each consume,
// so every graph replay starts clean.
__device__ float g_cls_raw[BB];
__device__ float g_reg_raw[BB];
__device__ int   g_numpos[BB];
__device__ unsigned int g_done;

__device__ __forceinline__ float smooth_l1(float d) {
    const float BETA = 1.0f / 9.0f;
    float ad = fabsf(d);
    return (ad <= BETA) ? (4.5f * ad * ad) : (ad - 0.5f * BETA);
}

// focal bulk term for one float4 of probabilities: sum p^2 * log2(1-p)
__device__ __forceinline__ float focal4(float4 p4) {
    return p4.x * p4.x * __log2f(1.0f - p4.x)
         + p4.y * p4.y * __log2f(1.0f - p4.y)
         + p4.z * p4.z * __log2f(1.0f - p4.z)
         + p4.w * p4.w * __log2f(1.0f - p4.w);
}

__global__ __launch_bounds__(TPB, 8) void retina_fused_kernel(
    const float* __restrict__ logits,   // (B,A,K)
    const float* __restrict__ regp,     // (B,A,4)
    const float* __restrict__ anchors,  // (A,4)
    const float* __restrict__ boxes,    // (B,M,4)
    const int*   __restrict__ cls,      // (B,M)
    float* __restrict__ out)
{
    const int b = blockIdx.y;
    const int tid = threadIdx.x;
    const int aStart = blockIdx.x * ANCH_PER_BLK;
    const int a = aStart + tid;
    const int aCnt = min(ANCH_PER_BLK, AA - aStart);

    __shared__ float4 sbox[MM];            // box coords
    __shared__ float4 saux[MM];            // (2/7)sb, (1/3)sb, sb, cls-bits
    __shared__ float  swgt[ANCH_PER_BLK];  // 1.0 if anchor contributes cls loss
    __shared__ int    splist[ANCH_PER_BLK];
    __shared__ int    spcnt;
    __shared__ float  wsum[8], wsum2[8];

    if (tid == 0) spcnt = 0;
    if (tid < MM) {
        float4 bx = ((const float4*)boxes)[b * MM + tid];
        float sb = (bx.z - bx.x) * (bx.w - bx.y);
        sbox[tid] = bx;
        float4 au;
        au.x = sb * (2.0f / 7.0f);   // 0.4/(1+0.4) * sb
        au.y = sb * (1.0f / 3.0f);   // 0.5/(1+0.5) * sb
        au.z = sb;
        au.w = __int_as_float(cls[b * MM + tid]);
        saux[tid] = au;
    }
    __syncthreads();

    float s = 0.0f;      // classification partial (units of p^2*log2(...))
    float rsum = 0.0f;   // regression partial

    // ---------- phase 1: cheap screen (11 ops/box via FFMA fusion) ----------
    // iou >= t  <=>  inter >= t/(1+t)*(sa+sb); inter - c = fma(iw, ih, -c).
    // Only iw is clamped: if ih<0 the fma under-estimates, and both
    // thresholds are strictly positive, so decisions are unchanged. Padded
    // boxes (-1) give iw=0 -> candidate -au <= 0: never flips anything.
    if (a < AA) {
        float4 an = ((const float4*)anchors)[a];
        const float ax1 = an.x, ay1 = an.y, ax2 = an.z, ay2 = an.w;
        const float sa = (ax2 - ax1) * (ay2 - ay1);

        float m4 = -1e30f, m5 = -1e30f;
        #pragma unroll 10
        for (int j = 0; j < MM; ++j) {
            float4 bx = sbox[j];
            float4 au = saux[j];
            float iw = fmaxf(fminf(ax2, bx.z) - fmaxf(ax1, bx.x), 0.0f);
            float ih = fminf(ay2, bx.w) - fmaxf(ay1, bx.y);
            m4 = fmaxf(m4, __fmaf_rn(iw, ih, -au.x));
            m5 = fmaxf(m5, __fmaf_rn(iw, ih, -au.y));
        }
        const bool pos = (m5 >= sa * (1.0f / 3.0f));   // iou_max >= 0.5
        const bool neg = (m4 <  sa * (2.0f / 7.0f));   // iou_max < 0.4
        swgt[tid] = (pos || neg) ? 1.0f : 0.0f;
        if (pos) splist[atomicAdd(&spcnt, 1)] = tid;
    } else {
        swgt[tid] = 0.0f;
    }
    __syncthreads();
    const int nposblk = spcnt;

    // ---------- phase 2: compacted positives (usually < 1 warp) ----------
    if (tid < nposblk) {
        const int at = splist[tid];
        const int ag = aStart + at;
        float4 an = ((const float4*)anchors)[ag];   // L1 hit
        const float ax1 = an.x, ay1 = an.y, ax2 = an.z, ay2 = an.w;
        const float aw = ax2 - ax1, ah = ay2 - ay1;
        const float sa = aw * ah;

        // division-free argmax of iou (first-max semantics preserved by '>')
        float bi = -1.0f, bu = 1.0f;
        int bj = 0;
        for (int j = 0; j < MM; ++j) {
            float4 bx = sbox[j];
            float iw = fmaxf(fminf(ax2, bx.z) - fmaxf(ax1, bx.x), 0.0f);
            float ih = fmaxf(fminf(ay2, bx.w) - fmaxf(ay1, bx.y), 0.0f);
            float inter = iw * ih;
            float ua = fmaxf(sa + saux[j].z - inter, 1e-8f);
            if (inter * bu > bi * ua) { bi = inter; bu = ua; bj = j; }
        }

        // focal correction on the positive class
        int c = __float_as_int(saux[bj].w) - 1;
        float praw = __ldg(logits + ((size_t)b * AA + ag) * KK + c);
        float p = fminf(fmaxf(praw, 1e-4f), 1.0f - 1e-4f);
        float q = 1.0f - p;
        s += (1.0f / 3.0f) * q * q * __log2f(p) - p * p * __log2f(q);

        // regression smooth-L1
        float4 gb = sbox[bj];
        float acx = ax1 + 0.5f * aw;
        float acy = ay1 + 0.5f * ah;
        float gw0 = gb.z - gb.x, gh0 = gb.w - gb.y;
        float gcx = gb.x + 0.5f * gw0;
        float gcy = gb.y + 0.5f * gh0;
        float gw = fmaxf(gw0, 1.0f), gh = fmaxf(gh0, 1.0f);
        float4 rp = ((const float4*)regp)[b * AA + ag];
        float t0 = ((gcx - acx) / aw) * 10.0f;
        float t1 = ((gcy - acy) / ah) * 10.0f;
        float t2 = logf(gw / aw) * 5.0f;
        float t3 = logf(gh / ah) * 5.0f;
        rsum = smooth_l1(t0 - rp.x) + smooth_l1(t1 - rp.y)
             + smooth_l1(t2 - rp.z) + smooth_l1(t3 - rp.w);
    }

    // ---------- phase 3: coalesced focal sweep (weighted by swgt) ----------
    {
        const float4* tile4 = (const float4*)(logits + ((size_t)b * AA + aStart) * KK);
        if (aCnt == ANCH_PER_BLK) {
            // guardless fast path (191 of 192 x-blocks)
            #pragma unroll 5
            for (int k = 0; k < ANCH_PER_BLK * (KK / 4) / TPB; ++k) {
                int i = tid + k * TPB;
                float w = swgt[i / (KK / 4)];
                s += w * focal4(tile4[i]);
            }
        } else {
            const int n4 = aCnt * (KK / 4);
            for (int i = tid; i < n4; i += TPB) {
                float w = swgt[i / (KK / 4)];
                s += w * focal4(tile4[i]);
            }
        }
    }

    // ---------- phase 4: block reduction, one atomic each ----------
    #pragma unroll
    for (int o = 16; o > 0; o >>= 1) {
        s    += __shfl_down_sync(0xffffffffu, s, o);
        rsum += __shfl_down_sync(0xffffffffu, rsum, o);
    }
    int lane = tid & 31, wid = tid >> 5;
    if (lane == 0) { wsum[wid] = s; wsum2[wid] = rsum; }
    __syncthreads();

    if (tid == 0) {
        float t = 0.0f, t2 = 0.0f;
        #pragma unroll
        for (int i = 0; i < 8; ++i) { t += wsum[i]; t2 += wsum2[i]; }
        if (t != 0.0f)  atomicAdd(&g_cls_raw[b], t);
        if (t2 != 0.0f) atomicAdd(&g_reg_raw[b], t2);
        if (nposblk)    atomicAdd(&g_numpos[b], nposblk);

        // ---------- phase 5: last block finalizes + resets ----------
        __threadfence();
        unsigned int prev = atomicAdd(&g_done, 1u);
        if (prev == NBLKS - 1) {
            float cm = 0.0f, rm = 0.0f;
            #pragma unroll
            for (int bb = 0; bb < BB; ++bb) {
                float np = fmaxf((float)g_numpos[bb], 1.0f);
                cm += (-0.75f * 0.69314718055994531f) * g_cls_raw[bb] / np;
                rm += g_reg_raw[bb] / (4.0f * np);
                g_cls_raw[bb] = 0.0f;
                g_reg_raw[bb] = 0.0f;
                g_numpos[bb] = 0;
            }
            cm *= (1.0f / (float)BB);
            rm *= (1.0f / (float)BB);
            out[0] = cm;
            out[1] = rm;
            out[2] = cm + rm;
            g_done = 0u;
        }
    }
}

extern "C" void kernel_launch(void* const* d_in, const int* in_sizes, int n_in,
                              void* d_out, int out_size) {
    const float* logits  = (const float*)d_in[0];
    const float* regp    = (const float*)d_in[1];
    const float* anchors = (const float*)d_in[2];
    const float* boxes   = (const float*)d_in[3];
    const int*   cls     = (const int*)d_in[4];
    float* out = (float*)d_out;

    dim3 grid(NBLKX, BB);
    retina_fused_kernel<<<grid, TPB>>>(logits, regp, anchors, boxes, cls, out);
}

// round 8
// speedup vs baseline: 1.3805x; 1.1979x over previous
#include <cuda_runtime.h>
#include <math.h>

#define BB 8
#define AA 49104
#define MM 50
#define KK 80
#define TPB 256
#define ANCH_PER_BLK 256
#define NBLKX ((AA + ANCH_PER_BLK - 1) / ANCH_PER_BLK)   // 192
#define NBLKS (NBLKX * BB)                               // 1536

// zero-initialized at module load; finalizer re-zeros after each consume,
// so every graph replay starts clean.
__device__ float g_cls_raw[BB];
__device__ float g_reg_raw[BB];
__device__ int   g_numpos[BB];
__device__ unsigned int g_done;

__device__ __forceinline__ float smooth_l1(float d) {
    const float BETA = 1.0f / 9.0f;
    float ad = fabsf(d);
    return (ad <= BETA) ? (4.5f * ad * ad) : (ad - 0.5f * BETA);
}

// focal bulk term for one float4 of probabilities: sum p^2 * log2(1-p)
__device__ __forceinline__ float focal4(float4 p4) {
    return p4.x * p4.x * __log2f(1.0f - p4.x)
         + p4.y * p4.y * __log2f(1.0f - p4.y)
         + p4.z * p4.z * __log2f(1.0f - p4.z)
         + p4.w * p4.w * __log2f(1.0f - p4.w);
}

__global__ __launch_bounds__(TPB, 6) void retina_fused_kernel(
    const float* __restrict__ logits,   // (B,A,K)
    const float* __restrict__ regp,     // (B,A,4)
    const float* __restrict__ anchors,  // (A,4)
    const float* __restrict__ boxes,    // (B,M,4)
    const int*   __restrict__ cls,      // (B,M)
    float* __restrict__ out)
{
    const int b = blockIdx.y;
    const int tid = threadIdx.x;
    const int aStart = blockIdx.x * ANCH_PER_BLK;
    const int a = aStart + tid;
    const int aCnt = min(ANCH_PER_BLK, AA - aStart);

    __shared__ float4 sbox[MM];            // box coords
    __shared__ float4 saux[MM];            // (2/7)sb, (1/3)sb, sb, cls-bits
    __shared__ float  swgt[ANCH_PER_BLK];  // 1.0 if anchor contributes cls loss
    __shared__ int    splist[ANCH_PER_BLK];
    __shared__ int    spcnt, snv;
    __shared__ float  wsum[8], wsum2[8];

    if (tid == 0) { spcnt = 0; snv = MM; }
    __syncthreads();
    if (tid < MM) {
        float4 bx = ((const float4*)boxes)[b * MM + tid];
        float sb = (bx.z - bx.x) * (bx.w - bx.y);
        sbox[tid] = bx;
        float4 au;
        au.x = sb * (2.0f / 7.0f);   // 0.4/(1+0.4) * sb
        au.y = sb * (1.0f / 3.0f);   // 0.5/(1+0.5) * sb
        au.z = sb;
        au.w = __int_as_float(cls[b * MM + tid]);
        saux[tid] = au;
        // valid-first padding: nv = index of first padded box
        if (bx.x == -1.0f) atomicMin(&snv, tid);
    }
    __syncthreads();
    const int nv = snv;   // uniform across block -> no divergence

    float s = 0.0f;      // classification partial (units of p^2*log2(...))
    float rsum = 0.0f;   // regression partial

    // ---------- phase 1: cheap screen over VALID boxes only ----------
    // iou >= t  <=>  inter >= t/(1+t)*(sa+sb); inter - c = fma(iw, ih, -c).
    // Only iw is clamped: if ih<0 the fma under-estimates, and both
    // thresholds are strictly positive, so decisions are unchanged.
    if (a < AA) {
        float4 an = ((const float4*)anchors)[a];
        const float ax1 = an.x, ay1 = an.y, ax2 = an.z, ay2 = an.w;
        const float sa = (ax2 - ax1) * (ay2 - ay1);

        float m4 = -1e30f, m5 = -1e30f;
        #pragma unroll 5
        for (int j = 0; j < nv; ++j) {
            float4 bx = sbox[j];
            float4 au = saux[j];
            float iw = fmaxf(fminf(ax2, bx.z) - fmaxf(ax1, bx.x), 0.0f);
            float ih = fminf(ay2, bx.w) - fmaxf(ay1, bx.y);
            m4 = fmaxf(m4, __fmaf_rn(iw, ih, -au.x));
            m5 = fmaxf(m5, __fmaf_rn(iw, ih, -au.y));
        }
        const bool pos = (m5 >= sa * (1.0f / 3.0f));   // iou_max >= 0.5
        const bool neg = (m4 <  sa * (2.0f / 7.0f));   // iou_max < 0.4
        swgt[tid] = (pos || neg) ? 1.0f : 0.0f;
        if (pos) splist[atomicAdd(&spcnt, 1)] = tid;
    } else {
        swgt[tid] = 0.0f;
    }
    __syncthreads();
    const int nposblk = spcnt;

    // ---------- phase 2: compacted positives (usually < 1 warp) ----------
    if (tid < nposblk) {
        const int at = splist[tid];
        const int ag = aStart + at;
        float4 an = ((const float4*)anchors)[ag];   // L1 hit
        const float ax1 = an.x, ay1 = an.y, ax2 = an.z, ay2 = an.w;
        const float aw = ax2 - ax1, ah = ay2 - ay1;
        const float sa = aw * ah;

        // division-free argmax of iou (first-max semantics preserved by '>')
        float bi = -1.0f, bu = 1.0f;
        int bj = 0;
        for (int j = 0; j < nv; ++j) {
            float4 bx = sbox[j];
            float iw = fmaxf(fminf(ax2, bx.z) - fmaxf(ax1, bx.x), 0.0f);
            float ih = fmaxf(fminf(ay2, bx.w) - fmaxf(ay1, bx.y), 0.0f);
            float inter = iw * ih;
            float ua = fmaxf(sa + saux[j].z - inter, 1e-8f);
            if (inter * bu > bi * ua) { bi = inter; bu = ua; bj = j; }
        }

        // focal correction on the positive class
        int c = __float_as_int(saux[bj].w) - 1;
        float praw = __ldg(logits + ((size_t)b * AA + ag) * KK + c);
        float p = fminf(fmaxf(praw, 1e-4f), 1.0f - 1e-4f);
        float q = 1.0f - p;
        s += (1.0f / 3.0f) * q * q * __log2f(p) - p * p * __log2f(q);

        // regression smooth-L1
        float4 gb = sbox[bj];
        float acx = ax1 + 0.5f * aw;
        float acy = ay1 + 0.5f * ah;
        float gw0 = gb.z - gb.x, gh0 = gb.w - gb.y;
        float gcx = gb.x + 0.5f * gw0;
        float gcy = gb.y + 0.5f * gh0;
        float gw = fmaxf(gw0, 1.0f), gh = fmaxf(gh0, 1.0f);
        float4 rp = ((const float4*)regp)[b * AA + ag];
        float t0 = ((gcx - acx) / aw) * 10.0f;
        float t1 = ((gcy - acy) / ah) * 10.0f;
        float t2 = logf(gw / aw) * 5.0f;
        float t3 = logf(gh / ah) * 5.0f;
        rsum = smooth_l1(t0 - rp.x) + smooth_l1(t1 - rp.y)
             + smooth_l1(t2 - rp.z) + smooth_l1(t3 - rp.w);
    }

    // ---------- phase 3: coalesced focal sweep (weighted by swgt) ----------
    {
        const float4* tile4 = (const float4*)(logits + ((size_t)b * AA + aStart) * KK);
        if (aCnt == ANCH_PER_BLK) {
            // guardless fast path (191 of 192 x-blocks)
            #pragma unroll 5
            for (int k = 0; k < ANCH_PER_BLK * (KK / 4) / TPB; ++k) {
                int i = tid + k * TPB;
                float w = swgt[i / (KK / 4)];
                s += w * focal4(tile4[i]);
            }
        } else {
            const int n4 = aCnt * (KK / 4);
            for (int i = tid; i < n4; i += TPB) {
                float w = swgt[i / (KK / 4)];
                s += w * focal4(tile4[i]);
            }
        }
    }

    // ---------- phase 4: block reduction, one atomic each ----------
    #pragma unroll
    for (int o = 16; o > 0; o >>= 1) {
        s    += __shfl_down_sync(0xffffffffu, s, o);
        rsum += __shfl_down_sync(0xffffffffu, rsum, o);
    }
    int lane = tid & 31, wid = tid >> 5;
    if (lane == 0) { wsum[wid] = s; wsum2[wid] = rsum; }
    __syncthreads();

    if (tid == 0) {
        float t = 0.0f, t2 = 0.0f;
        #pragma unroll
        for (int i = 0; i < 8; ++i) { t += wsum[i]; t2 += wsum2[i]; }
        if (t != 0.0f)  atomicAdd(&g_cls_raw[b], t);
        if (t2 != 0.0f) atomicAdd(&g_reg_raw[b], t2);
        if (nposblk)    atomicAdd(&g_numpos[b], nposblk);

        // ---------- phase 5: last block finalizes + resets ----------
        __threadfence();
        unsigned int prev = atomicAdd(&g_done, 1u);
        if (prev == NBLKS - 1) {
            float cm = 0.0f, rm = 0.0f;
            #pragma unroll
            for (int bb = 0; bb < BB; ++bb) {
                float np = fmaxf((float)g_numpos[bb], 1.0f);
                cm += (-0.75f * 0.69314718055994531f) * g_cls_raw[bb] / np;
                rm += g_reg_raw[bb] / (4.0f * np);
                g_cls_raw[bb] = 0.0f;
                g_reg_raw[bb] = 0.0f;
                g_numpos[bb] = 0;
            }
            cm *= (1.0f / (float)BB);
            rm *= (1.0f / (float)BB);
            out[0] = cm;
            out[1] = rm;
            out[2] = cm + rm;
            g_done = 0u;
        }
    }
}

extern "C" void kernel_launch(void* const* d_in, const int* in_sizes, int n_in,
                              void* d_out, int out_size) {
    const float* logits  = (const float*)d_in[0];
    const float* regp    = (const float*)d_in[1];
    const float* anchors = (const float*)d_in[2];
    const float* boxes   = (const float*)d_in[3];
    const int*   cls     = (const int*)d_in[4];
    float* out = (float*)d_out;

    dim3 grid(NBLKX, BB);
    retina_fused_kernel<<<grid, TPB>>>(logits, regp, anchors, boxes, cls, out);
}